// round 1
// baseline (speedup 1.0000x reference)
#include <cuda_runtime.h>
#include <math.h>

// ---------------------------------------------------------------------------
// DeepSeek V3 MLA layer, fp32 baseline.
// B=2, T=1024, HID=4096, H=32, D_NOPE=128, D_ROPE=64, D_V=128, D_QK=192,
// Q_RANK=1536, KV_RANK=512.
// Pipeline:
//   1. qlow = x @ wq_a                      [2048,1536]
//   2. rmsnorm(qlow) (in place)
//   3. q    = qlow @ wq_b                   [2048,6144]  (H*D_QK)
//   4. kvout= x @ wkv_a                     [2048,576]   (KV_RANK + D_ROPE)
//   5. rmsnorm(kvout[:, :512]) in place
//   6. rope(q pe cols), rope(kvout[:,512:576])
//   7. kvexp= kvout[:, :512] @ wkv_b        [2048,8192]  (H*(D_NOPE+D_V))
//   8. scores[b,h] = scale * Qh @ [k_nope | k_pe]^T  + causal/pad mask
//   9. row softmax over scores
//  10. attn_out[b,h] = scores[b,h] @ V_h    (causal-trimmed K loop)
//  11. out  = attn_out @ wo                 [2048,4096]
// ---------------------------------------------------------------------------

#define NTOK 2048            // B*T
#define TT   1024
#define NH   32

// device scratch (no cudaMalloc allowed)
__device__ float g_qlow [2048 * 1536];
__device__ float g_q    [2048 * 6144];
__device__ float g_kvout[2048 * 576];
__device__ float g_kvexp[2048 * 8192];
__device__ float g_scores[64ll * 1024 * 1024];   // [B*H][T][T] 268MB
__device__ float g_attn [2048 * 4096];

// ---------------------------------------------------------------------------
// Generic NN SGEMM: C[M,N] = A[M,K] @ B[K,N]. 128x128x16 tiles, 8x8 micro.
// Batched via blockIdx.z with (outer, inner) stride decomposition.
// causal != 0: limit K to (m0 + 128)  (valid keys for causal attention rows).
// M must be a multiple of 128; N,K arbitrary (N guarded; K multiple of 16).
// ---------------------------------------------------------------------------
__global__ void __launch_bounds__(256, 2) gemm_nn_k(
    const float* __restrict__ Ab, const float* __restrict__ Bb,
    float* __restrict__ Cb,
    int M, int N, int K, int lda, int ldb, int ldc,
    long aOut, long aIn, long bOut, long bIn, long cOut, long cIn,
    int innerCount, int causal)
{
    int z = blockIdx.z;
    int outer = z / innerCount, inner = z - outer * innerCount;
    const float* A = Ab + (long)outer * aOut + (long)inner * aIn;
    const float* B = Bb + (long)outer * bOut + (long)inner * bIn;
    float*       C = Cb + (long)outer * cOut + (long)inner * cIn;

    __shared__ float As[16][128];
    __shared__ float Bs[16][128];

    int tid = threadIdx.x;
    int tx = tid & 15, ty = tid >> 4;
    int m0 = blockIdx.y * 128, n0 = blockIdx.x * 128;

    int Keff = causal ? min(K, m0 + 128) : K;

    float acc[8][8] = {};

    for (int k0 = 0; k0 < Keff; k0 += 16) {
        // A tile: rows m0..m0+127, k0..k0+15 -> As[k][m]
#pragma unroll
        for (int i = 0; i < 2; i++) {
            int idx = tid * 2 + i;
            int row = idx >> 2, kc = (idx & 3) << 2;
            float4 v = *(const float4*)(A + (long)(m0 + row) * lda + k0 + kc);
            As[kc + 0][row] = v.x;
            As[kc + 1][row] = v.y;
            As[kc + 2][row] = v.z;
            As[kc + 3][row] = v.w;
        }
        // B tile: rows k0..k0+15, cols n0..n0+127 -> Bs[k][n]
#pragma unroll
        for (int i = 0; i < 2; i++) {
            int idx = tid * 2 + i;
            int kr = idx >> 5, nc = (idx & 31) << 2;
            int n = n0 + nc;
            float4 v;
            if (n + 3 < N) {
                v = *(const float4*)(B + (long)(k0 + kr) * ldb + n);
            } else {
                const float* bp = B + (long)(k0 + kr) * ldb;
                v.x = (n + 0 < N) ? bp[n + 0] : 0.f;
                v.y = (n + 1 < N) ? bp[n + 1] : 0.f;
                v.z = (n + 2 < N) ? bp[n + 2] : 0.f;
                v.w = 0.f;
            }
            *(float4*)&Bs[kr][nc] = v;
        }
        __syncthreads();
#pragma unroll
        for (int k = 0; k < 16; k++) {
            float ra[8], rb[8];
            *(float4*)&ra[0] = *(const float4*)&As[k][ty * 8];
            *(float4*)&ra[4] = *(const float4*)&As[k][ty * 8 + 4];
            *(float4*)&rb[0] = *(const float4*)&Bs[k][tx * 8];
            *(float4*)&rb[4] = *(const float4*)&Bs[k][tx * 8 + 4];
#pragma unroll
            for (int i = 0; i < 8; i++)
#pragma unroll
                for (int j = 0; j < 8; j++)
                    acc[i][j] = fmaf(ra[i], rb[j], acc[i][j]);
        }
        __syncthreads();
    }

#pragma unroll
    for (int i = 0; i < 8; i++) {
        int m = m0 + ty * 8 + i;
#pragma unroll
        for (int j = 0; j < 8; j++) {
            int n = n0 + tx * 8 + j;
            if (n < N) C[(long)m * ldc + n] = acc[i][j];
        }
    }
}

// ---------------------------------------------------------------------------
// Scores: S[b,h][t][s] = scale * ( q_nope . k_nope + q_pe . k_pe ),
// masked to -1e30 above diagonal / where attention_mask==0.
// NT GEMM with gathered K operand (k_nope from kvexp, k_pe shared from kvout).
// ---------------------------------------------------------------------------
__global__ void __launch_bounds__(256, 2) scores_k(
    const float* __restrict__ q, const float* __restrict__ kvexp,
    const float* __restrict__ kvout, const int* __restrict__ amask,
    float* __restrict__ scores)
{
    int bh = blockIdx.z, b = bh >> 5, h = bh & 31;
    int m0 = blockIdx.y * 128, n0 = blockIdx.x * 128;
    float* C = scores + (long)bh * TT * TT;

    if (n0 >= m0 + 128) {          // fully above causal diagonal
        for (int e = threadIdx.x; e < 128 * 128; e += 256) {
            int i = e >> 7, j = e & 127;
            C[(long)(m0 + i) * TT + n0 + j] = -1e30f;
        }
        return;
    }

    const float* A  = q     + (long)b * TT * 6144 + h * 192;  // lda 6144
    const float* Kn = kvexp + (long)b * TT * 8192 + h * 256;  // ld 8192
    const float* Kp = kvout + (long)b * TT * 576  + 512;      // ld 576

    __shared__ float As[16][128];
    __shared__ float Bs[16][128];
    int tid = threadIdx.x, tx = tid & 15, ty = tid >> 4;

    float acc[8][8] = {};
    for (int k0 = 0; k0 < 192; k0 += 16) {
#pragma unroll
        for (int i = 0; i < 2; i++) {
            int idx = tid * 2 + i;
            int row = idx >> 2, kc = (idx & 3) << 2;
            float4 v = *(const float4*)(A + (long)(m0 + row) * 6144 + k0 + kc);
            As[kc + 0][row] = v.x;
            As[kc + 1][row] = v.y;
            As[kc + 2][row] = v.z;
            As[kc + 3][row] = v.w;
        }
#pragma unroll
        for (int i = 0; i < 2; i++) {
            int idx = tid * 2 + i;
            int row = idx >> 2, kc = (idx & 3) << 2;
            int kk = k0 + kc, s = n0 + row;
            float4 v;
            if (kk < 128) v = *(const float4*)(Kn + (long)s * 8192 + kk);
            else          v = *(const float4*)(Kp + (long)s * 576 + (kk - 128));
            Bs[kc + 0][row] = v.x;
            Bs[kc + 1][row] = v.y;
            Bs[kc + 2][row] = v.z;
            Bs[kc + 3][row] = v.w;
        }
        __syncthreads();
#pragma unroll
        for (int k = 0; k < 16; k++) {
            float ra[8], rb[8];
            *(float4*)&ra[0] = *(const float4*)&As[k][ty * 8];
            *(float4*)&ra[4] = *(const float4*)&As[k][ty * 8 + 4];
            *(float4*)&rb[0] = *(const float4*)&Bs[k][tx * 8];
            *(float4*)&rb[4] = *(const float4*)&Bs[k][tx * 8 + 4];
#pragma unroll
            for (int i = 0; i < 8; i++)
#pragma unroll
                for (int j = 0; j < 8; j++)
                    acc[i][j] = fmaf(ra[i], rb[j], acc[i][j]);
        }
        __syncthreads();
    }

    const float scale = 0.07216878364870323f;   // 192^-0.5
#pragma unroll
    for (int i = 0; i < 8; i++) {
        int t = m0 + ty * 8 + i;
#pragma unroll
        for (int j = 0; j < 8; j++) {
            int s = n0 + tx * 8 + j;
            float v = acc[i][j] * scale;
            if (s > t || amask[b * TT + s] == 0) v = -1e30f;
            C[(long)t * TT + s] = v;
        }
    }
}

// ---------------------------------------------------------------------------
// Row softmax over 1024 columns; one block (256 threads, 4 cols each) per row.
// ---------------------------------------------------------------------------
__global__ void softmax_k(float* __restrict__ scores)
{
    __shared__ float red[256];
    long row = blockIdx.x;
    float* p = scores + row * TT;
    int tid = threadIdx.x;
    float4 v = *(float4*)(p + tid * 4);
    float m = fmaxf(fmaxf(v.x, v.y), fmaxf(v.z, v.w));
    red[tid] = m; __syncthreads();
    for (int s = 128; s > 0; s >>= 1) {
        if (tid < s) red[tid] = fmaxf(red[tid], red[tid + s]);
        __syncthreads();
    }
    m = red[0]; __syncthreads();
    v.x = expf(v.x - m); v.y = expf(v.y - m);
    v.z = expf(v.z - m); v.w = expf(v.w - m);
    red[tid] = v.x + v.y + v.z + v.w; __syncthreads();
    for (int s = 128; s > 0; s >>= 1) {
        if (tid < s) red[tid] += red[tid + s];
        __syncthreads();
    }
    float inv = 1.0f / red[0];
    v.x *= inv; v.y *= inv; v.z *= inv; v.w *= inv;
    *(float4*)(p + tid * 4) = v;
}

// ---------------------------------------------------------------------------
// RMSNorm over first n columns of each row (row stride ld), in place.
// ---------------------------------------------------------------------------
__global__ void rmsnorm_k(float* __restrict__ x, const float* __restrict__ w,
                          int n, int ld)
{
    __shared__ float red[256];
    long row = blockIdx.x;
    float* p = x + row * ld;
    int tid = threadIdx.x;
    float ss = 0.f;
    for (int c = tid; c < n; c += 256) { float v = p[c]; ss += v * v; }
    red[tid] = ss; __syncthreads();
    for (int s = 128; s > 0; s >>= 1) {
        if (tid < s) red[tid] += red[tid + s];
        __syncthreads();
    }
    float r = rsqrtf(red[0] / (float)n + 1e-6f);
    for (int c = tid; c < n; c += 256) p[c] = p[c] * r * w[c];
}

// ---------------------------------------------------------------------------
// RoPE on q pe columns: per (token, head), cols [h*192+128, h*192+192).
// half-split: x1 = [0,32), x2 = [32,64).
// ---------------------------------------------------------------------------
__global__ void rope_q_k(float* __restrict__ q, const int* __restrict__ pos)
{
    int gid = blockIdx.x * 256 + threadIdx.x;   // B*T*H*32 = 2097152 threads
    int i = gid & 31;
    int row = gid >> 5;          // bt*32 + h
    int h = row & 31, bt = row >> 5;
    float p = (float)pos[bt];
    float invf = powf(10000.f, -(float)i / 32.f);
    float sn, cs;
    sincosf(p * invf, &sn, &cs);
    float* base = q + (long)bt * 6144 + h * 192 + 128;
    float x1 = base[i], x2 = base[32 + i];
    base[i]      = x1 * cs - x2 * sn;
    base[32 + i] = x1 * sn + x2 * cs;
}

// RoPE on shared key pe: kvout cols [512, 576) per token.
__global__ void rope_kpe_k(float* __restrict__ kvout, const int* __restrict__ pos)
{
    int gid = blockIdx.x * 256 + threadIdx.x;   // B*T*32 = 65536 threads
    int i = gid & 31;
    int bt = gid >> 5;
    float p = (float)pos[bt];
    float invf = powf(10000.f, -(float)i / 32.f);
    float sn, cs;
    sincosf(p * invf, &sn, &cs);
    float* base = kvout + (long)bt * 576 + 512;
    float x1 = base[i], x2 = base[32 + i];
    base[i]      = x1 * cs - x2 * sn;
    base[32 + i] = x1 * sn + x2 * cs;
}

// ---------------------------------------------------------------------------
extern "C" void kernel_launch(void* const* d_in, const int* in_sizes, int n_in,
                              void* d_out, int out_size)
{
    const float* x        = (const float*)d_in[0];
    const float* wq_a     = (const float*)d_in[1];
    const float* q_norm_w = (const float*)d_in[2];
    const float* wq_b     = (const float*)d_in[3];
    const float* wkv_a    = (const float*)d_in[4];
    const float* kv_norm_w= (const float*)d_in[5];
    const float* wkv_b    = (const float*)d_in[6];
    const float* wo       = (const float*)d_in[7];
    const int*   amask    = (const int*)d_in[8];
    const int*   pos      = (const int*)d_in[9];
    float*       out      = (float*)d_out;

    float *qlow, *qq, *kvout, *kvexp, *scores, *attn;
    cudaGetSymbolAddress((void**)&qlow,   g_qlow);
    cudaGetSymbolAddress((void**)&qq,     g_q);
    cudaGetSymbolAddress((void**)&kvout,  g_kvout);
    cudaGetSymbolAddress((void**)&kvexp,  g_kvexp);
    cudaGetSymbolAddress((void**)&scores, g_scores);
    cudaGetSymbolAddress((void**)&attn,   g_attn);

    dim3 blk(256);

    // 1. qlow = x @ wq_a          [2048,1536]
    gemm_nn_k<<<dim3(12, 16, 1), blk>>>(x, wq_a, qlow,
        2048, 1536, 4096, 4096, 1536, 1536, 0, 0, 0, 0, 0, 0, 1, 0);
    // 2. rmsnorm(qlow)
    rmsnorm_k<<<2048, 256>>>(qlow, q_norm_w, 1536, 1536);
    // 3. q = qlow @ wq_b          [2048,6144]
    gemm_nn_k<<<dim3(48, 16, 1), blk>>>(qlow, wq_b, qq,
        2048, 6144, 1536, 1536, 6144, 6144, 0, 0, 0, 0, 0, 0, 1, 0);
    // 4. kvout = x @ wkv_a        [2048,576]
    gemm_nn_k<<<dim3(5, 16, 1), blk>>>(x, wkv_a, kvout,
        2048, 576, 4096, 4096, 576, 576, 0, 0, 0, 0, 0, 0, 1, 0);
    // 5. rmsnorm(kvout[:, :512])
    rmsnorm_k<<<2048, 256>>>(kvout, kv_norm_w, 512, 576);
    // 6. rope
    rope_q_k<<<8192, 256>>>(qq, pos);
    rope_kpe_k<<<256, 256>>>(kvout, pos);
    // 7. kvexp = kvout[:, :512] @ wkv_b   [2048,8192]
    gemm_nn_k<<<dim3(64, 16, 1), blk>>>(kvout, wkv_b, kvexp,
        2048, 8192, 512, 576, 8192, 8192, 0, 0, 0, 0, 0, 0, 1, 0);
    // 8. scores
    scores_k<<<dim3(8, 8, 64), blk>>>(qq, kvexp, kvout, amask, scores);
    // 9. softmax rows
    softmax_k<<<65536, 256>>>(scores);
    // 10. attn_out = scores @ V (batched over b,h; causal K trim)
    gemm_nn_k<<<dim3(1, 8, 64), blk>>>(scores, kvexp + 128, attn,
        1024, 128, 1024, 1024, 8192, 4096,
        (long)32 * 1024 * 1024, (long)1024 * 1024,
        (long)1024 * 8192, 256,
        (long)1024 * 4096, 128,
        32, 1);
    // 11. out = attn_out @ wo     [2048,4096]
    gemm_nn_k<<<dim3(32, 16, 1), blk>>>(attn, wo, out,
        2048, 4096, 4096, 4096, 4096, 4096, 0, 0, 0, 0, 0, 0, 1, 0);
}